// round 14
// baseline (speedup 1.0000x reference)
#include <cuda_runtime.h>
#include <cuda_bf16.h>
#include <cstdint>

// RetinaFace decode, N = 1e6 priors. Fully pipelined:
//  - input tiles (64 priors = 4KB) prefetched via cp.async.bulk + mbarrier,
//    double-buffered: tile k+1 loads while tile k computes (latency hidden by
//    prefetch depth instead of warp count / per-thread MLP).
//  - outputs staged in SMEM (double-buffered) and drained via bulk stores.
// Pair mapping inside a tile: 2 threads per prior,
//   role 0: loc(4) + {c0,c1,lm0x,lm0y} -> box, conf, det rows 0-1
//   role 1: {lm1,lm2} + {lm3,lm4}      -> det rows 2-3
//
// Output layout (float32):
//   [0,4N) boxes_m | [4N,5N) conf_m | [5N,6N) pred_m(=0) | [6N,22N) det | [22N,23N) keep

#define T_TILES 4          // tiles per block
#define TILE_PRIORS 64
#define TILE_IN_BYTES 4096 // 64 priors * 64B

// staging buffer layout (bytes)
#define SG_DET  0
#define SG_BOX  4096
#define SG_CONF 5120
#define SG_PRED 5376
#define SG_KEEP 5632
#define SG_TOT  5888

__device__ __forceinline__ void bulk_store(void* gdst, uint32_t ssrc, uint32_t bytes) {
    asm volatile("cp.async.bulk.global.shared::cta.bulk_group [%0], [%1], %2;"
                 :: "l"(gdst), "r"(ssrc), "r"(bytes) : "memory");
}
__device__ __forceinline__ void bulk_load(uint32_t sdst, const void* gsrc,
                                          uint32_t bytes, uint32_t mbar) {
    asm volatile("cp.async.bulk.shared::cta.global.mbarrier::complete_tx::bytes "
                 "[%0], [%1], %2, [%3];"
                 :: "r"(sdst), "l"(gsrc), "r"(bytes), "r"(mbar) : "memory");
}
__device__ __forceinline__ void mbar_init(uint32_t mbar, uint32_t cnt) {
    asm volatile("mbarrier.init.shared.b64 [%0], %1;" :: "r"(mbar), "r"(cnt) : "memory");
}
__device__ __forceinline__ void mbar_expect_tx(uint32_t mbar, uint32_t bytes) {
    asm volatile("mbarrier.arrive.expect_tx.shared.b64 _, [%0], %1;"
                 :: "r"(mbar), "r"(bytes) : "memory");
}
__device__ __forceinline__ void mbar_wait(uint32_t mbar, uint32_t parity) {
    asm volatile(
        "{\n\t"
        ".reg .pred P1;\n\t"
        "WAIT_LOOP_%=:\n\t"
        "mbarrier.try_wait.parity.acquire.cta.shared::cta.b64 P1, [%0], %1, 0x989680;\n\t"
        "@P1 bra.uni WAIT_DONE_%=;\n\t"
        "bra.uni WAIT_LOOP_%=;\n\t"
        "WAIT_DONE_%=:\n\t"
        "}"
        :: "r"(mbar), "r"(parity) : "memory");
}

__global__ __launch_bounds__(128) void retina_decode_pipe(
    const float* __restrict__ in,       // [N,16]
    const float4* __restrict__ priors,  // [N]
    const float* __restrict__ thr,
    const float* __restrict__ var,
    float* __restrict__ out,
    int N, int nTiles)
{
    __shared__ __align__(16) unsigned char inbuf[2][TILE_IN_BYTES];
    __shared__ __align__(16) unsigned char stage[2][SG_TOT];
    __shared__ __align__(8)  unsigned long long mbar_sto[2];

    const int t   = threadIdx.x;           // 0..127
    const int r   = t & 1;                 // role
    const int ql  = t >> 1;                // local prior 0..63
    const int tileBase = blockIdx.x * T_TILES;
    if (tileBase >= nTiles) return;

    const uint32_t smb0 = (uint32_t)__cvta_generic_to_shared(&mbar_sto[0]);
    const uint32_t smb1 = smb0 + 8;
    const uint32_t sin0 = (uint32_t)__cvta_generic_to_shared(&inbuf[0][0]);
    const uint32_t sin1 = (uint32_t)__cvta_generic_to_shared(&inbuf[1][0]);

    // prologue: init mbarriers, issue first load
    if (t == 0) {
        mbar_init(smb0, 1);
        mbar_init(smb1, 1);
        asm volatile("fence.proxy.async.shared::cta;" ::: "memory");
        mbar_expect_tx(smb0, TILE_IN_BYTES);
        bulk_load(sin0, in + (size_t)tileBase * 1024, TILE_IN_BYTES, smb0);
    }
    __syncthreads();

    const float v0 = var[0];
    const float v1 = var[1];
    const float th = thr[0];
    const size_t Ns = (size_t)N;

    #pragma unroll
    for (int k = 0; k < T_TILES; k++) {
        int tile = tileBase + k;
        if (tile >= nTiles) break;

        if (t == 0) {
            // prefetch next tile
            if (k + 1 < T_TILES && tile + 1 < nTiles) {
                uint32_t mb = ((k + 1) & 1) ? smb1 : smb0;
                uint32_t sb = ((k + 1) & 1) ? sin1 : sin0;
                mbar_expect_tx(mb, TILE_IN_BYTES);
                bulk_load(sb, in + (size_t)(tile + 1) * 1024, TILE_IN_BYTES, mb);
            }
            // ensure staging[k&1]'s previous store group has been read out
            asm volatile("cp.async.bulk.wait_group.read 1;" ::: "memory");
        }
        // wait for this tile's input
        mbar_wait((k & 1) ? smb1 : smb0, (k >> 1) & 1);
        __syncthreads();   // staging-free + input-ready visible to all

        // ---- compute from SMEM ----
        const unsigned char* ib = inbuf[k & 1];
        float4 lo = *reinterpret_cast<const float4*>(ib + 32 * t);
        float4 hi = *reinterpret_cast<const float4*>(ib + 32 * t + 16);
        int q = tile * TILE_PRIORS + ql;
        float4 p = priors[q];

        // class scores: role-0 lane's hi = {c0, c1, lm0x, lm0y}
        float diff = __shfl_sync(0xffffffffu, hi.y - hi.x, 0, 2);
        float conf = 1.0f / (1.0f + __expf(-fabsf(diff)));
        bool  keep = (diff > 0.0f) && (conf > th);
        float mf   = keep ? 1.0f : 0.0f;
        float confm = conf * mf;

        float sx = v0 * p.z;
        float sy = v0 * p.w;

        unsigned char* sg = stage[k & 1];
        float4 d_lo, d_hi;
        if (r == 0) {
            float cx = p.x + lo.x * sx;
            float cy = p.y + lo.y * sy;
            float w  = p.z * __expf(lo.z * v1);
            float h  = p.w * __expf(lo.w * v1);
            float x0 = cx - 0.5f * w;
            float y0 = cy - 0.5f * h;
            float x1 = x0 + w;
            float y1 = y0 + h;
            d_lo = make_float4(x0 * mf, y0 * mf, x1 * mf, y1 * mf);  // box
            d_hi = make_float4(confm, 0.0f,
                               (p.x + hi.z * sx) * mf, (p.y + hi.w * sy) * mf);
            *reinterpret_cast<float4*>(sg + SG_BOX + 16 * ql) = d_lo;
            *reinterpret_cast<float*>(sg + SG_CONF + 4 * ql)  = confm;
        } else {
            d_lo = make_float4((p.x + lo.x * sx) * mf, (p.y + lo.y * sy) * mf,
                               (p.x + lo.z * sx) * mf, (p.y + lo.w * sy) * mf);
            d_hi = make_float4((p.x + hi.x * sx) * mf, (p.y + hi.y * sy) * mf,
                               (p.x + hi.z * sx) * mf, (p.y + hi.w * sy) * mf);
            *reinterpret_cast<float*>(sg + SG_PRED + 4 * ql) = 0.0f;
            *reinterpret_cast<float*>(sg + SG_KEEP + 4 * ql) = mf;
        }
        *reinterpret_cast<float4*>(sg + SG_DET + 32 * t)      = d_lo;
        *reinterpret_cast<float4*>(sg + SG_DET + 32 * t + 16) = d_hi;

        __syncthreads();   // staging complete

        if (t == 0) {
            uint32_t sgb = (uint32_t)__cvta_generic_to_shared(sg);
            asm volatile("fence.proxy.async.shared::cta;" ::: "memory");
            bulk_store(out + 6 * Ns + (size_t)1024 * tile, sgb + SG_DET, 4096);
            bulk_store(out + (size_t)256 * tile,           sgb + SG_BOX, 1024);
            bulk_store(out + 4 * Ns + (size_t)64 * tile,   sgb + SG_CONF, 256);
            bulk_store(out + 5 * Ns + (size_t)64 * tile,   sgb + SG_PRED, 256);
            bulk_store(out + 22 * Ns + (size_t)64 * tile,  sgb + SG_KEEP, 256);
            asm volatile("cp.async.bulk.commit_group;" ::: "memory");
        }
    }

    if (t == 0)
        asm volatile("cp.async.bulk.wait_group.read 0;" ::: "memory");
}

// tail kernel for N % 64 != 0 (not hit for N = 1e6)
__global__ void retina_decode_tail(
    const float* __restrict__ in, const float4* __restrict__ priors,
    const float* __restrict__ thr, const float* __restrict__ var,
    float* __restrict__ out, int N, int start)
{
    int q = start + blockIdx.x * blockDim.x + threadIdx.x;
    if (q >= N) return;
    const float v0 = var[0], v1 = var[1], th = thr[0];
    const float* row = in + (size_t)16 * q;
    float4 p = priors[q];
    float diff = row[5] - row[4];
    float conf = 1.0f / (1.0f + __expf(-fabsf(diff)));
    bool keep = (diff > 0.0f) && (conf > th);
    float mf = keep ? 1.0f : 0.0f;
    float sx = v0 * p.z, sy = v0 * p.w;
    float cx = p.x + row[0] * sx, cy = p.y + row[1] * sy;
    float w = p.z * __expf(row[2] * v1), h = p.w * __expf(row[3] * v1);
    float x0 = cx - 0.5f * w, y0 = cy - 0.5f * h;
    size_t Ns = (size_t)N;
    float4 box = make_float4(x0 * mf, y0 * mf, (x0 + w) * mf, (y0 + h) * mf);
    reinterpret_cast<float4*>(out)[q] = box;
    out[4 * Ns + q] = conf * mf;
    out[5 * Ns + q] = 0.0f;
    out[22 * Ns + q] = mf;
    float* det = out + 6 * Ns + (size_t)16 * q;
    det[0] = box.x; det[1] = box.y; det[2] = box.z; det[3] = box.w;
    det[4] = conf * mf; det[5] = 0.0f;
    #pragma unroll
    for (int l = 0; l < 5; l++) {
        det[6 + 2 * l]     = (p.x + row[6 + 2 * l] * sx) * mf;
        det[7 + 2 * l]     = (p.y + row[7 + 2 * l] * sy) * mf;
    }
}

extern "C" void kernel_launch(void* const* d_in, const int* in_sizes, int n_in,
                              void* d_out, int out_size)
{
    const float*  in     = (const float*)d_in[0];
    const float*  thr    = (const float*)d_in[1];
    const float4* priors = (const float4*)d_in[2];
    const float*  var    = (const float*)d_in[3];
    float* out = (float*)d_out;

    int N = in_sizes[2] / 4;          // priors is [N,4]
    int nTiles = N / TILE_PRIORS;     // full tiles
    int blocks = (nTiles + T_TILES - 1) / T_TILES;
    if (blocks > 0)
        retina_decode_pipe<<<blocks, 128>>>(in, priors, thr, var, out, N, nTiles);
    int rem = N - nTiles * TILE_PRIORS;
    if (rem > 0)
        retina_decode_tail<<<1, 64>>>(in, priors, thr, var, out, N, nTiles * TILE_PRIORS);
}

// round 15
// speedup vs baseline: 1.0990x; 1.0990x over previous
#include <cuda_runtime.h>
#include <cuda_bf16.h>
#include <cstdint>

// RetinaFace decode, N = 1e6 priors. R13 structure with 2x block size:
// 128 priors / 256 threads per block; outputs staged in SMEM and drained
// via cp.async.bulk (det burst 8KB, boxes 2KB, scalars 512B) for longer
// DRAM bursts and half the per-block sync/issue overhead.
// Pair mapping: 2 threads per prior, 256-bit evict_last loads.
//   role 0: loc(4) + {c0,c1,lm0x,lm0y}  -> box, conf, det rows 0-1
//   role 1: {lm1,lm2} + {lm3,lm4}       -> det rows 2-3
//
// Output layout (float32):
//   [0,4N) boxes_m | [4N,5N) conf_m | [5N,6N) pred_m(=0) | [6N,22N) det | [22N,23N) keep

#define TILE_PRIORS 128
#define THREADS     256

struct U64x4 { unsigned long long a, b, c, d; };

__device__ __forceinline__ U64x4 ld_evl256(const void* p) {
    U64x4 v;
    asm("ld.global.L2::evict_last.v4.b64 {%0,%1,%2,%3}, [%4];"
        : "=l"(v.a), "=l"(v.b), "=l"(v.c), "=l"(v.d) : "l"(p));
    return v;
}
__device__ __forceinline__ void st_evf256(void* p, U64x4 v) {
    asm volatile("st.global.L2::evict_first.v4.b64 [%0], {%1,%2,%3,%4};"
                 :: "l"(p), "l"(v.a), "l"(v.b), "l"(v.c), "l"(v.d) : "memory");
}
__device__ __forceinline__ float2 unpack(unsigned long long u) {
    float2 f;
    asm("mov.b64 {%0,%1}, %2;" : "=f"(f.x), "=f"(f.y) : "l"(u));
    return f;
}
__device__ __forceinline__ unsigned long long pack(float x, float y) {
    unsigned long long u;
    asm("mov.b64 %0, {%1,%2};" : "=l"(u) : "f"(x), "f"(y));
    return u;
}
__device__ __forceinline__ void bulk_store(void* gdst, uint32_t ssrc, uint32_t bytes) {
    asm volatile("cp.async.bulk.global.shared::cta.bulk_group [%0], [%1], %2;"
                 :: "l"(gdst), "r"(ssrc), "r"(bytes) : "memory");
}

// SMEM staging layout (bytes): det 8192 | boxes 2048 | conf 512 | pred 512 | keep 512
#define SM_DET  0
#define SM_BOX  8192
#define SM_CONF 10240
#define SM_PRED 10752
#define SM_KEEP 11264
#define SM_TOT  11776

__global__ __launch_bounds__(THREADS) void retina_decode_kernel(
    const float* __restrict__ in,       // [N,16]
    const float4* __restrict__ priors,  // [N] float4
    const float* __restrict__ thr,
    const float* __restrict__ var,
    float* __restrict__ out,
    int N)
{
    __shared__ __align__(16) unsigned char sm[SM_TOT];

    const int t   = threadIdx.x;             // 0..255
    const int blk = blockIdx.x;
    const int r   = t & 1;                   // role
    const int ql  = t >> 1;                  // local prior 0..127
    const int q   = blk * TILE_PRIORS + ql;  // global prior
    const size_t half = (size_t)blk * (2 * TILE_PRIORS) + t;  // global half-row

    const bool active = (q < N);
    const bool full   = (blk * TILE_PRIORS + TILE_PRIORS) <= N;

    const float v0 = var[0];
    const float v1 = var[1];
    const float th = thr[0];

    U64x4 vin = {0, 0, 0, 0};
    float4 p  = make_float4(0.f, 0.f, 1.f, 1.f);
    if (active) {
        vin = ld_evl256(in + 8 * half);
        p   = priors[q];
    }
    float2 f0 = unpack(vin.a);
    float2 f1 = unpack(vin.b);
    float2 f2 = unpack(vin.c);
    float2 f3 = unpack(vin.d);

    // class scores live in role-0 lane's .c = {c0, c1}: broadcast width-2
    float diff = __shfl_sync(0xffffffffu, f2.y - f2.x, 0, 2);
    float conf = 1.0f / (1.0f + __expf(-fabsf(diff)));
    bool  keep = (diff > 0.0f) && (conf > th);
    float mf   = keep ? 1.0f : 0.0f;
    float confm = conf * mf;

    float sx = v0 * p.z;
    float sy = v0 * p.w;

    size_t Ns = (size_t)N;
    U64x4 det_half;
    float4 box;

    if (r == 0) {
        float cx = p.x + f0.x * sx;
        float cy = p.y + f0.y * sy;
        float w  = p.z * __expf(f1.x * v1);
        float h  = p.w * __expf(f1.y * v1);
        float x0 = cx - 0.5f * w;
        float y0 = cy - 0.5f * h;
        float x1 = x0 + w;
        float y1 = y0 + h;
        box = make_float4(x0 * mf, y0 * mf, x1 * mf, y1 * mf);
        det_half.a = pack(box.x, box.y);
        det_half.b = pack(box.z, box.w);
        det_half.c = pack(confm, 0.0f);
        det_half.d = pack((p.x + f3.x * sx) * mf, (p.y + f3.y * sy) * mf);
    } else {
        det_half.a = pack((p.x + f0.x * sx) * mf, (p.y + f0.y * sy) * mf);
        det_half.b = pack((p.x + f1.x * sx) * mf, (p.y + f1.y * sy) * mf);
        det_half.c = pack((p.x + f2.x * sx) * mf, (p.y + f2.y * sy) * mf);
        det_half.d = pack((p.x + f3.x * sx) * mf, (p.y + f3.y * sy) * mf);
    }

    if (full) {
        // ---- stage outputs in SMEM ----
        ulonglong2* dp = reinterpret_cast<ulonglong2*>(sm + SM_DET + 32 * t);
        dp[0] = make_ulonglong2(det_half.a, det_half.b);
        dp[1] = make_ulonglong2(det_half.c, det_half.d);
        if (r == 0) {
            reinterpret_cast<float4*>(sm + SM_BOX)[ql] = box;
            reinterpret_cast<float*>(sm + SM_CONF)[ql] = confm;
        } else {
            reinterpret_cast<float*>(sm + SM_PRED)[ql] = 0.0f;
            reinterpret_cast<float*>(sm + SM_KEEP)[ql] = mf;
        }
        __syncthreads();

        if (t == 0) {
            uint32_t sbase = (uint32_t)__cvta_generic_to_shared(sm);
            asm volatile("fence.proxy.async.shared::cta;" ::: "memory");
            bulk_store(out + 6 * Ns + (size_t)2048 * blk, sbase + SM_DET, 8192);
            bulk_store(out + (size_t)512 * blk,           sbase + SM_BOX, 2048);
            bulk_store(out + 4 * Ns + (size_t)128 * blk,  sbase + SM_CONF, 512);
            bulk_store(out + 5 * Ns + (size_t)128 * blk,  sbase + SM_PRED, 512);
            bulk_store(out + 22 * Ns + (size_t)128 * blk, sbase + SM_KEEP, 512);
            asm volatile("cp.async.bulk.commit_group;" ::: "memory");
            asm volatile("cp.async.bulk.wait_group.read 0;" ::: "memory");
        }
    } else if (active) {
        // tail block (64 priors for N = 1e6): direct stores
        st_evf256(out + 6 * Ns + 8 * half, det_half);
        if (r == 0) {
            reinterpret_cast<float4*>(out)[q] = box;
            out[4 * Ns + q] = confm;
        } else {
            out[5 * Ns + q]  = 0.0f;
            out[22 * Ns + q] = mf;
        }
    }
}

extern "C" void kernel_launch(void* const* d_in, const int* in_sizes, int n_in,
                              void* d_out, int out_size)
{
    const float*  in     = (const float*)d_in[0];
    const float*  thr    = (const float*)d_in[1];
    const float4* priors = (const float4*)d_in[2];
    const float*  var    = (const float*)d_in[3];
    float* out = (float*)d_out;

    int N = in_sizes[2] / 4;   // priors is [N,4]

    int blocks = (N + TILE_PRIORS - 1) / TILE_PRIORS;   // 1e6 -> 7813 (last partial)
    retina_decode_kernel<<<blocks, THREADS>>>(in, priors, thr, var, out, N);
}